// round 2
// baseline (speedup 1.0000x reference)
#include <cuda_runtime.h>

// 4-D multilinear interpolation on an 8x8x8x8 lattice.
// coordinates: [32768, 4] float32 in [0,1]
// mesh_pred:   [32768, 4096] float32 (each point has its own lattice row)
// out:         [32768] float32
//
// Strides (row-major over mesh dims [8,8,8,8]): dim0=512, dim1=64, dim2=8, dim3=1.

#define BATCH 32768
#define VOLUME 4096

__global__ __launch_bounds__(256, 8)
void HL_41996190220467_kernel(const float4* __restrict__ coords,
                              const float* __restrict__ mesh,
                              float* __restrict__ out)
{
    int b = blockIdx.x * blockDim.x + threadIdx.x;
    if (b >= BATCH) return;   // defensive; grid is sized exactly so always false

    float4 c4 = coords[b];

    float c0 = c4.x * 7.0f;
    float c1 = c4.y * 7.0f;
    float c2 = c4.z * 7.0f;
    float c3 = c4.w * 7.0f;

    int i0 = min(max((int)c0, 0), 6);
    int i1 = min(max((int)c1, 0), 6);
    int i2 = min(max((int)c2, 0), 6);
    int i3 = min(max((int)c3, 0), 6);

    float f0 = c0 - (float)i0;
    float f1 = c1 - (float)i1;
    float f2 = c2 - (float)i2;
    float f3 = c3 - (float)i3;

    const float* __restrict__ row = mesh + (size_t)b * VOLUME;
    int base = i0 * 512 + i1 * 64 + i2 * 8 + i3;

    // 16 independent loads, corner index k = d0*8 + d1*4 + d2*2 + d3
    // offset(k) = d0*512 + d1*64 + d2*8 + d3
    float v[16];
#pragma unroll
    for (int k = 0; k < 16; k++) {
        int off = ((k >> 3) & 1) * 512
                + ((k >> 2) & 1) * 64
                + ((k >> 1) & 1) * 8
                + (k & 1);
        v[k] = __ldg(row + base + off);
    }

    // Reduce along dim3 (adjacent k), then dim2, dim1, dim0.
    float a[8];
#pragma unroll
    for (int k = 0; k < 8; k++) a[k] = fmaf(f3, v[2 * k + 1] - v[2 * k], v[2 * k]);
    float s[4];
#pragma unroll
    for (int k = 0; k < 4; k++) s[k] = fmaf(f2, a[2 * k + 1] - a[2 * k], a[2 * k]);
    float t0 = fmaf(f1, s[1] - s[0], s[0]);
    float t1 = fmaf(f1, s[3] - s[2], s[2]);
    out[b] = fmaf(f0, t1 - t0, t0);
}

extern "C" void kernel_launch(void* const* d_in, const int* in_sizes, int n_in,
                              void* d_out, int out_size)
{
    const float4* coords = (const float4*)d_in[0];   // [32768, 4] -> float4 per point
    const float*  mesh   = (const float*)d_in[1];    // [32768, 4096]
    float* out = (float*)d_out;                      // [32768]
    (void)in_sizes; (void)n_in; (void)out_size;

    // 32768 points / 256 threads = 128 CTAs, one thread per point.
    HL_41996190220467_kernel<<<BATCH / 256, 256>>>(coords, mesh, out);
}

// round 3
// speedup vs baseline: 1.0048x; 1.0048x over previous
#include <cuda_runtime.h>

// 4-D multilinear interpolation on an 8x8x8x8 lattice, 4 lanes per point.
// coordinates: [32768, 4] float32 in [0,1]
// mesh_pred:   [32768, 4096] float32 (each point has its own lattice row)
// out:         [32768] float32
//
// Strides (row-major over mesh dims [8,8,8,8]): dim0=512, dim1=64, dim2=8, dim3=1.
//
// Lane q = tid&3 owns (d0,d1) = (q>>1, q&1). It loads the two 8-float dim3
// segments (d2=0,1) for that octant. Each segment is 32B-aligned, and the
// needed pair {i3, i3+1} sits inside one aligned float4 at offset o=(i3>=4)?4:0
// except when i3==3 (one predicated scalar fixup). Partial results are summed
// across the 4 lanes with two butterfly shuffles.

#define BATCH  32768
#define VOLUME 4096

__global__ __launch_bounds__(256, 8)
void HL_41996190220467_kernel(const float4* __restrict__ coords,
                              const float* __restrict__ mesh,
                              float* __restrict__ out)
{
    int t = blockIdx.x * blockDim.x + threadIdx.x;
    int p = t >> 2;        // point index
    int q = t & 3;         // (d0,d1) octant-pair: d0 = q>>1, d1 = q&1

    float4 c4 = coords[p];         // 4 lanes of a point broadcast-load same 16B

    float c0 = c4.x * 7.0f;
    float c1 = c4.y * 7.0f;
    float c2 = c4.z * 7.0f;
    float c3 = c4.w * 7.0f;

    int i0 = min(max((int)c0, 0), 6);
    int i1 = min(max((int)c1, 0), 6);
    int i2 = min(max((int)c2, 0), 6);
    int i3 = min(max((int)c3, 0), 6);

    float f0 = c0 - (float)i0;
    float f1 = c1 - (float)i1;
    float f2 = c2 - (float)i2;
    float f3 = c3 - (float)i3;

    const float* __restrict__ row = mesh + (size_t)p * VOLUME;

    // segment base for this lane's (d0,d1), at d2 = i2 (multiple of 8 floats)
    int s0 = i0 * 512 + i1 * 64 + i2 * 8
           + ((q >> 1) ? 512 : 0) + ((q & 1) ? 64 : 0);

    int o = (i3 >= 4) ? 4 : 0;     // which aligned float4 half of the segment
    int l = i3 - o;                // local index of pair start, 0..3 (3 only if i3==3)

    // d2=0 and d2=1 pair regions (both 16B aligned)
    float4 A = *reinterpret_cast<const float4*>(row + s0 + o);
    float4 B = *reinterpret_cast<const float4*>(row + s0 + 8 + o);

    // fixup element (local index 4) needed only when i3==3 (then o==0)
    bool  fix = (l == 3);
    float a4 = fix ? __ldg(row + s0 + 4)  : 0.0f;
    float b4 = fix ? __ldg(row + s0 + 12) : 0.0f;

    // select pair (v0,v1) from A, (w0,w1) from B
    float v0 = (l == 0) ? A.x : (l == 1) ? A.y : (l == 2) ? A.z : A.w;
    float v1 = (l == 0) ? A.y : (l == 1) ? A.z : (l == 2) ? A.w : a4;
    float w0 = (l == 0) ? B.x : (l == 1) ? B.y : (l == 2) ? B.z : B.w;
    float w1 = (l == 0) ? B.y : (l == 1) ? B.z : (l == 2) ? B.w : b4;

    // lerp dim3 then dim2
    float u0 = fmaf(f3, v1 - v0, v0);
    float u1 = fmaf(f3, w1 - w0, w0);
    float tq = fmaf(f2, u1 - u0, u0);

    // weight for this lane's (d0,d1)
    float wq = ((q >> 1) ? f0 : 1.0f - f0) * ((q & 1) ? f1 : 1.0f - f1);
    float r  = tq * wq;

    // sum across the 4 lanes of this point
    r += __shfl_xor_sync(0xffffffffu, r, 1);
    r += __shfl_xor_sync(0xffffffffu, r, 2);

    if (q == 0) out[p] = r;
}

extern "C" void kernel_launch(void* const* d_in, const int* in_sizes, int n_in,
                              void* d_out, int out_size)
{
    const float4* coords = (const float4*)d_in[0];   // [32768, 4]
    const float*  mesh   = (const float*)d_in[1];    // [32768, 4096]
    float* out = (float*)d_out;                      // [32768]
    (void)in_sizes; (void)n_in; (void)out_size;

    // 32768 points * 4 lanes = 131072 threads = 512 CTAs of 256
    HL_41996190220467_kernel<<<(BATCH * 4) / 256, 256>>>(coords, mesh, out);
}